// round 2
// baseline (speedup 1.0000x reference)
#include <cuda_runtime.h>
#include <math.h>

// Problem constants
#define U_ 8192
#define P_ 4096
#define D_ 64
#define B_ 1024
#define H_ 50

// ---------------- scratch (device globals; no allocations allowed) ----------
__device__ float g_u1[5L * U_ * D_];   // u1[r] = A_r @ p0           (10.5 MB)
__device__ float g_p1[5L * P_ * D_];   // p1[r] = A_r^T @ u0         ( 5.25 MB)
__device__ float g_Xu[5L * U_ * D_];   // Xu[r] = (u0+u1+u2)/3       (10.5 MB)
__device__ float g_p2[4L * P_ * D_];   // split-K partials of A0^T @ u1[0]
__device__ float g_var[U_];
__device__ float g_uemb[(long)U_ * D_];

struct Ptr5 { const float* p[5]; };

// ---------------------------------------------------------------------------
// Generic GEMM: C[M x 64] = op(A) @ X,  op(A)=A (M x K) or A^T (A is K x M)
//   grid.x: M/128 tiles, grid.y: K-split index, grid.z: relation r
//   EPI 0: C = acc
//   EPI 1: C = (E1 + E2 + acc) / 3     (fused Xu epilogue)
// Two-level accumulation: a 32-k tile is accumulated in lacc (small magnitude),
// then folded into acc — keeps fp32 rounding error ~sub-ulp w.r.t. the cosines.
// ---------------------------------------------------------------------------
template<bool TRANS, int EPI>
__global__ __launch_bounds__(256) void gemm64_kernel(
    Ptr5 a5, int ldA,
    const float* __restrict__ Xbase, long strideX,
    float* __restrict__ Cbase, long strideCz, long strideCy,
    const float* __restrict__ E1,
    const float* __restrict__ E2base, long strideE2,
    int Kchunk)
{
    const int r = blockIdx.z;
    const float* __restrict__ A = a5.p[r];
    const float* __restrict__ X = Xbase + (long)r * strideX;
    float* __restrict__ C = Cbase + (long)r * strideCz + (long)blockIdx.y * strideCy;

    const int m0 = blockIdx.x * 128;
    const int kBegin = blockIdx.y * Kchunk;
    const int kEnd = kBegin + Kchunk;

    __shared__ float As[32][128 + 4];   // As[k][m]
    __shared__ float Xs[32][64];        // Xs[k][n]

    const int tid = threadIdx.x;
    const int tm = tid >> 4;   // 0..15 -> m = tm*8 + i
    const int tn = tid & 15;   // 0..15 -> n = tn*4 + j

    float acc[8][4];
#pragma unroll
    for (int i = 0; i < 8; i++)
#pragma unroll
        for (int j = 0; j < 4; j++) acc[i][j] = 0.0f;

    for (int k0 = kBegin; k0 < kEnd; k0 += 32) {
        if (!TRANS) {
            // tile: 128 m-rows x 32 k, row-major in gmem -> transpose into As[k][m]
#pragma unroll
            for (int f = 0; f < 4; f++) {
                int linear = tid + 256 * f;
                int row = linear >> 3;
                int c4  = (linear & 7) * 4;
                float4 v = *(const float4*)(A + (size_t)(m0 + row) * ldA + k0 + c4);
                As[c4 + 0][row] = v.x;
                As[c4 + 1][row] = v.y;
                As[c4 + 2][row] = v.z;
                As[c4 + 3][row] = v.w;
            }
        } else {
            // A is K x M (row-major): tile rows are k, m contiguous -> direct store
#pragma unroll
            for (int f = 0; f < 4; f++) {
                int linear = tid + 256 * f;
                int kk = linear >> 5;
                int m4 = (linear & 31) * 4;
                float4 v = *(const float4*)(A + (size_t)(k0 + kk) * ldA + m0 + m4);
                *(float4*)&As[kk][m4] = v;
            }
        }
        // X tile: 32 x 64
#pragma unroll
        for (int f = 0; f < 2; f++) {
            int linear = tid + 256 * f;
            int kk = linear >> 4;
            int n4 = (linear & 15) * 4;
            *(float4*)&Xs[kk][n4] = *(const float4*)(X + (size_t)(k0 + kk) * 64 + n4);
        }
        __syncthreads();

        float lacc[8][4];
#pragma unroll
        for (int i = 0; i < 8; i++)
#pragma unroll
            for (int j = 0; j < 4; j++) lacc[i][j] = 0.0f;

#pragma unroll
        for (int k = 0; k < 32; k++) {
            float4 aA = *(const float4*)&As[k][tm * 8];
            float4 aB = *(const float4*)&As[k][tm * 8 + 4];
            float a[8] = {aA.x, aA.y, aA.z, aA.w, aB.x, aB.y, aB.z, aB.w};
            float4 bv = *(const float4*)&Xs[k][tn * 4];
            float b[4] = {bv.x, bv.y, bv.z, bv.w};
#pragma unroll
            for (int i = 0; i < 8; i++)
#pragma unroll
                for (int j = 0; j < 4; j++)
                    lacc[i][j] += a[i] * b[j];
        }

#pragma unroll
        for (int i = 0; i < 8; i++)
#pragma unroll
            for (int j = 0; j < 4; j++) acc[i][j] += lacc[i][j];

        __syncthreads();
    }

    // epilogue
#pragma unroll
    for (int i = 0; i < 8; i++) {
        int m = m0 + tm * 8 + i;
        long off = (long)m * 64 + tn * 4;
        float4 v;
        if (EPI == 0) {
            v.x = acc[i][0]; v.y = acc[i][1]; v.z = acc[i][2]; v.w = acc[i][3];
        } else {
            const float* __restrict__ e2 = E2base + (long)r * strideE2;
            v.x = (E1[off + 0] + e2[off + 0] + acc[i][0]) / 3.0f;
            v.y = (E1[off + 1] + e2[off + 1] + acc[i][1]) / 3.0f;
            v.z = (E1[off + 2] + e2[off + 2] + acc[i][2]) / 3.0f;
            v.w = (E1[off + 3] + e2[off + 3] + acc[i][3]) / 3.0f;
        }
        *(float4*)(C + off) = v;
    }
}

// ---------------------------------------------------------------------------
// Per-user: cosine sims vs 4 relations -> var[u]; user_embedding[u] = W[u,:]@rel
// One warp per user; lane covers d and d+32. All reductions in fp64 so the
// fp32-rounded sims reproduce the TRUE tie pattern of (sim == max).
// ---------------------------------------------------------------------------
__global__ __launch_bounds__(256) void user_kernel(const float* __restrict__ W)
{
    const int warp = threadIdx.x >> 5;
    const int lane = threadIdx.x & 31;
    const int u = blockIdx.x * 8 + warp;

    const float* __restrict__ xu0 = g_Xu + (long)u * 64;
    const float b0f = xu0[lane], b1f = xu0[lane + 32];
    const double b0 = (double)b0f, b1 = (double)b1f;

    double d0 = b0 * b0 + b1 * b1;
#pragma unroll
    for (int o = 16; o; o >>= 1) d0 += __shfl_xor_sync(0xffffffffu, d0, o);
    const double n0 = sqrt(d0);

    float sims[4], x0s[4], x1s[4];
#pragma unroll
    for (int rr = 0; rr < 4; rr++) {
        const float* __restrict__ xr = g_Xu + (long)(rr + 1) * U_ * D_ + (long)u * 64;
        float x0 = xr[lane], x1 = xr[lane + 32];
        x0s[rr] = x0; x1s[rr] = x1;
        double xd0 = (double)x0, xd1 = (double)x1;
        double c = b0 * xd0 + b1 * xd1;
        double n = xd0 * xd0 + xd1 * xd1;
#pragma unroll
        for (int o = 16; o; o >>= 1) {
            c += __shfl_xor_sync(0xffffffffu, c, o);
            n += __shfl_xor_sync(0xffffffffu, n, o);
        }
        double denom = n0 * sqrt(n);
        denom = (denom > 1e-8) ? denom : 1e-8;
        sims[rr] = (float)(c / denom);   // round to fp32: reproduces fp32 ties
    }

    if (lane == 0) {
        float mx = fmaxf(fmaxf(sims[0], sims[1]), fmaxf(sims[2], sims[3]));
        double s[4], sum = 0.0;
#pragma unroll
        for (int rr = 0; rr < 4; rr++) {
            s[rr] = (sims[rr] == mx) ? (double)sims[rr] : 0.0;
            sum += s[rr];
        }
        double mean = sum * 0.25;
        double ss = 0.0;
#pragma unroll
        for (int rr = 0; rr < 4; rr++) { double dd = s[rr] - mean; ss += dd * dd; }
        double stdv = sqrt(ss * (1.0 / 3.0));   // ddof=1
        g_var[u] = (float)log(stdv + 1.0);
    }

    const float w0 = W[u * 4 + 0], w1 = W[u * 4 + 1];
    const float w2 = W[u * 4 + 2], w3 = W[u * 4 + 3];
    g_uemb[(long)u * 64 + lane]      = w0 * x0s[0] + w1 * x0s[1] + w2 * x0s[2] + w3 * x0s[3];
    g_uemb[(long)u * 64 + lane + 32] = w0 * x1s[0] + w1 * x1s[1] + w2 * x1s[2] + w3 * x1s[3];
}

// ---------------------------------------------------------------------------
// Gather + output. One block per batch element, 64 threads (one per d).
// Output layout: [X_post | X_var_user | AugUser | X_mean_user], each B x D.
// ---------------------------------------------------------------------------
__global__ __launch_bounds__(64) void gather_kernel(
    const float* __restrict__ post_emb,
    const int* __restrict__ src_id,
    const int* __restrict__ rum_id,
    float* __restrict__ out)
{
    const int b = blockIdx.x;
    const int d = threadIdx.x;

    // X_post = (p0 + p1[0] + p2)/3 gathered at src
    int s = src_id[b];
    long soff = (long)s * 64 + d;
    float p2 = g_p2[soff] + g_p2[1L * P_ * D_ + soff]
             + g_p2[2L * P_ * D_ + soff] + g_p2[3L * P_ * D_ + soff];
    out[(long)b * 64 + d] = (post_emb[soff] + g_p1[soff] + p2) / 3.0f;

    float accv = 0.0f, accm = 0.0f, accu = 0.0f;
#pragma unroll 2
    for (int h = 0; h < H_; h++) {
        int id = rum_id[b * H_ + h];
        long off = (long)id * 64 + d;
        float x = g_Xu[off];            // base = Xu[0]
        float v = g_var[id];
        accv += v * x;
        accm += x;
        accu += g_uemb[off];
    }
    const long BD = (long)B_ * D_;
    out[BD     + (long)b * 64 + d] = accv;
    out[2 * BD + (long)b * 64 + d] = accu * (1.0f / H_);
    out[3 * BD + (long)b * 64 + d] = accm * (1.0f / H_);
}

// ---------------------------------------------------------------------------
extern "C" void kernel_launch(void* const* d_in, const int* in_sizes, int n_in,
                              void* d_out, int out_size)
{
    const float* A0        = (const float*)d_in[0];
    const float* A1        = (const float*)d_in[1];
    const float* A2        = (const float*)d_in[2];
    const float* A3        = (const float*)d_in[3];
    const float* A4        = (const float*)d_in[4];
    const float* user_emb  = (const float*)d_in[5];
    const float* post_emb  = (const float*)d_in[6];
    const float* user_model= (const float*)d_in[7];
    const int*   src_id    = (const int*)d_in[8];
    // d_in[9] = X_user_id (unused by the reference)
    const int*   rum_id    = (const int*)d_in[10];
    float* out = (float*)d_out;

    float *pu1, *pp1, *pXu, *pp2;
    cudaGetSymbolAddress((void**)&pu1, g_u1);
    cudaGetSymbolAddress((void**)&pp1, g_p1);
    cudaGetSymbolAddress((void**)&pXu, g_Xu);
    cudaGetSymbolAddress((void**)&pp2, g_p2);

    Ptr5 a5; a5.p[0] = A0; a5.p[1] = A1; a5.p[2] = A2; a5.p[3] = A3; a5.p[4] = A4;

    const long UD = (long)U_ * D_;
    const long PD = (long)P_ * D_;

    // 1) u1[r] = A_r @ p0              (M=U, K=P)
    gemm64_kernel<false, 0><<<dim3(U_ / 128, 1, 5), 256>>>(
        a5, P_, post_emb, 0, pu1, UD, 0, nullptr, nullptr, 0, P_);

    // 2) p1[r] = A_r^T @ u0            (M=P, K=U)
    gemm64_kernel<true, 0><<<dim3(P_ / 128, 1, 5), 256>>>(
        a5, P_, user_emb, 0, pp1, PD, 0, nullptr, nullptr, 0, U_);

    // 3) Xu[r] = (u0 + u1[r] + A_r @ p1[r]) / 3
    gemm64_kernel<false, 1><<<dim3(U_ / 128, 1, 5), 256>>>(
        a5, P_, pp1, PD, pXu, UD, 0, user_emb, pu1, UD, P_);

    // 4) p2 partials = A0^T @ u1[0], deterministic split-K=4 (z=0 -> A0)
    gemm64_kernel<true, 0><<<dim3(P_ / 128, 4, 1), 256>>>(
        a5, P_, pu1, 0, pp2, 0, PD, nullptr, nullptr, 0, U_ / 4);

    // 5) per-user var + user_embedding (fp64 cosine chain)
    user_kernel<<<U_ / 8, 256>>>(user_model);

    // 6) gather outputs
    gather_kernel<<<B_, 64>>>(post_emb, src_id, rum_id, out);
}

// round 3
// speedup vs baseline: 1.1120x; 1.1120x over previous
#include <cuda_runtime.h>
#include <math.h>

// Problem constants
#define U_ 8192
#define P_ 4096
#define D_ 64
#define B_ 1024
#define H_ 50

typedef unsigned long long ull;

// Packed fp32x2 ops (sm_103a). Each is two independent fp32 ops -> bitwise
// identical to scalar FFMA/FADD per element. ptxas never emits these from C++.
#define FMA2(d, a, b) asm("fma.rn.f32x2 %0, %1, %2, %0;" : "+l"(d) : "l"(a), "l"(b))
#define ADD2(d, s)    asm("add.rn.f32x2 %0, %1, %0;" : "+l"(d) : "l"(s))
#define DUP2(d, s)    asm("mov.b64 %0, {%1, %1};"    : "=l"(d) : "f"(s))

// ---------------- scratch (device globals; no allocations allowed) ----------
__device__ float g_u1[5L * U_ * D_];   // u1[r] = A_r @ p0           (10.5 MB)
__device__ float g_p1[5L * P_ * D_];   // p1[r] = A_r^T @ u0         ( 5.25 MB)
__device__ float g_Xu[5L * U_ * D_];   // Xu[r] = (u0+u1+u2)/3       (10.5 MB)
__device__ float g_p2[4L * P_ * D_];   // split-K partials of A0^T @ u1[0]
__device__ float g_var[U_];
__device__ float g_uemb[(long)U_ * D_];

struct Ptr5 { const float* p[5]; };

// ---------------------------------------------------------------------------
// GEMM: C[M x 64] = op(A) @ X,  op(A)=A (M x K) or A^T (A is K x M)
//   BM: 128 (thread tile 8m x 4n) or 64 (thread tile 8m x 2n), 256 threads.
//   grid.x: M/BM tiles, grid.y: K-split index, grid.z: relation r
//   EPI 0: C = acc;  EPI 1: C = (E1 + E2 + acc) / 3
// Per-element FP order is IDENTICAL to the round-2 kernel:
//   k0 tiles of 32 in order; within a tile, 32 sequential fma.rn into lacc
//   (zero-initialized); then one add.rn into acc per tile. fma.rn.f32x2 packs
//   two adjacent-m elements per instruction without changing either lane.
// ---------------------------------------------------------------------------
template<bool TRANS, int EPI, int BM>
__global__ __launch_bounds__(256, 2) void gemm64_kernel(
    Ptr5 a5, int ldA,
    const float* __restrict__ Xbase, long strideX,
    float* __restrict__ Cbase, long strideCz, long strideCy,
    const float* __restrict__ E1,
    const float* __restrict__ E2base, long strideE2,
    int Kchunk)
{
    constexpr int RN = (BM == 128) ? 4 : 2;      // n-cols per thread
    const int r = blockIdx.z;
    const float* __restrict__ A = a5.p[r];
    const float* __restrict__ X = Xbase + (long)r * strideX;
    float* __restrict__ C = Cbase + (long)r * strideCz + (long)blockIdx.y * strideCy;

    const int m0 = blockIdx.x * BM;
    const int kBegin = blockIdx.y * Kchunk;
    const int kEnd = kBegin + Kchunk;

    __shared__ float As[32][BM + 4];   // As[k][m]
    __shared__ float Xs[32][64];       // Xs[k][n]

    const int tid = threadIdx.x;
    const int tm = (BM == 128) ? (tid >> 4) : (tid >> 5);
    const int tn = (BM == 128) ? (tid & 15) : (tid & 31);

    ull acc2[4][RN];                   // 4 m-pairs x RN cols, packed f32x2
#pragma unroll
    for (int p = 0; p < 4; p++)
#pragma unroll
        for (int j = 0; j < RN; j++) acc2[p][j] = 0ull;

    for (int k0 = kBegin; k0 < kEnd; k0 += 32) {
        if (!TRANS) {
            // A row-major M x K: tile BM rows x 32 k -> transpose into As[k][m]
#pragma unroll
            for (int f = 0; f < BM / 32; f++) {
                int linear = tid + 256 * f;
                int row = linear >> 3;
                int c4  = (linear & 7) * 4;
                float4 v = *(const float4*)(A + (size_t)(m0 + row) * ldA + k0 + c4);
                As[c4 + 0][row] = v.x;
                As[c4 + 1][row] = v.y;
                As[c4 + 2][row] = v.z;
                As[c4 + 3][row] = v.w;
            }
        } else {
            // A row-major K x M: rows are k, m contiguous -> direct store
            constexpr int PR = BM / 4;           // float4 per row
#pragma unroll
            for (int f = 0; f < BM / 32; f++) {
                int linear = tid + 256 * f;
                int kk = linear / PR;
                int m4 = (linear % PR) * 4;
                float4 v = *(const float4*)(A + (size_t)(k0 + kk) * ldA + m0 + m4);
                *(float4*)&As[kk][m4] = v;
            }
        }
        // X tile: 32 x 64
#pragma unroll
        for (int f = 0; f < 2; f++) {
            int linear = tid + 256 * f;
            int kk = linear >> 4;
            int n4 = (linear & 15) * 4;
            *(float4*)&Xs[kk][n4] = *(const float4*)(X + (size_t)(k0 + kk) * 64 + n4);
        }
        __syncthreads();

        ull lacc2[4][RN];
#pragma unroll
        for (int p = 0; p < 4; p++)
#pragma unroll
            for (int j = 0; j < RN; j++) lacc2[p][j] = 0ull;

#pragma unroll
        for (int k = 0; k < 32; k++) {
            const ull* ap = (const ull*)&As[k][tm * 8];   // 16B-aligned
            ull a0 = ap[0], a1 = ap[1], a2 = ap[2], a3 = ap[3];
            ull bb[RN];
            if (BM == 128) {
                float4 bv = *(const float4*)&Xs[k][tn * 4];
                DUP2(bb[0], bv.x); DUP2(bb[1], bv.y);
                DUP2(bb[2], bv.z); DUP2(bb[3], bv.w);
            } else {
                float2 bv = *(const float2*)&Xs[k][tn * 2];
                DUP2(bb[0], bv.x); DUP2(bb[1], bv.y);
            }
#pragma unroll
            for (int j = 0; j < RN; j++) {
                FMA2(lacc2[0][j], a0, bb[j]);
                FMA2(lacc2[1][j], a1, bb[j]);
                FMA2(lacc2[2][j], a2, bb[j]);
                FMA2(lacc2[3][j], a3, bb[j]);
            }
        }

#pragma unroll
        for (int p = 0; p < 4; p++)
#pragma unroll
            for (int j = 0; j < RN; j++) ADD2(acc2[p][j], lacc2[p][j]);

        __syncthreads();
    }

    // epilogue
#pragma unroll
    for (int p = 0; p < 4; p++) {
        float2 f[RN];
#pragma unroll
        for (int j = 0; j < RN; j++) f[j] = *(float2*)&acc2[p][j];
#pragma unroll
        for (int h = 0; h < 2; h++) {
            int m = m0 + tm * 8 + 2 * p + h;
            long off = (long)m * 64 + tn * RN;
            float vals[RN];
#pragma unroll
            for (int j = 0; j < RN; j++) vals[j] = h ? f[j].y : f[j].x;
            if (EPI == 1) {
                const float* __restrict__ e2 = E2base + (long)r * strideE2;
#pragma unroll
                for (int j = 0; j < RN; j++)
                    vals[j] = (E1[off + j] + e2[off + j] + vals[j]) / 3.0f;
            }
            if (RN == 4) {
                float4 v; v.x = vals[0]; v.y = vals[1]; v.z = vals[2]; v.w = vals[3];
                *(float4*)(C + off) = v;
            } else {
                float2 v; v.x = vals[0]; v.y = vals[1];
                *(float2*)(C + off) = v;
            }
        }
    }
}

// ---------------------------------------------------------------------------
// Per-user: cosine sims vs 4 relations -> var[u]; user_embedding[u] = W[u,:]@rel
// One warp per user; lane covers d and d+32. fp64 chain; round sims to fp32
// before the (sim == max) test to reproduce the fp32 tie pattern.
// ---------------------------------------------------------------------------
__global__ __launch_bounds__(256) void user_kernel(const float* __restrict__ W)
{
    const int warp = threadIdx.x >> 5;
    const int lane = threadIdx.x & 31;
    const int u = blockIdx.x * 8 + warp;

    const float* __restrict__ xu0 = g_Xu + (long)u * 64;
    const float b0f = xu0[lane], b1f = xu0[lane + 32];
    const double b0 = (double)b0f, b1 = (double)b1f;

    double d0 = b0 * b0 + b1 * b1;
#pragma unroll
    for (int o = 16; o; o >>= 1) d0 += __shfl_xor_sync(0xffffffffu, d0, o);
    const double n0 = sqrt(d0);

    float sims[4], x0s[4], x1s[4];
#pragma unroll
    for (int rr = 0; rr < 4; rr++) {
        const float* __restrict__ xr = g_Xu + (long)(rr + 1) * U_ * D_ + (long)u * 64;
        float x0 = xr[lane], x1 = xr[lane + 32];
        x0s[rr] = x0; x1s[rr] = x1;
        double xd0 = (double)x0, xd1 = (double)x1;
        double c = b0 * xd0 + b1 * xd1;
        double n = xd0 * xd0 + xd1 * xd1;
#pragma unroll
        for (int o = 16; o; o >>= 1) {
            c += __shfl_xor_sync(0xffffffffu, c, o);
            n += __shfl_xor_sync(0xffffffffu, n, o);
        }
        double denom = n0 * sqrt(n);
        denom = (denom > 1e-8) ? denom : 1e-8;
        sims[rr] = (float)(c / denom);
    }

    if (lane == 0) {
        float mx = fmaxf(fmaxf(sims[0], sims[1]), fmaxf(sims[2], sims[3]));
        double s[4], sum = 0.0;
#pragma unroll
        for (int rr = 0; rr < 4; rr++) {
            s[rr] = (sims[rr] == mx) ? (double)sims[rr] : 0.0;
            sum += s[rr];
        }
        double mean = sum * 0.25;
        double ss = 0.0;
#pragma unroll
        for (int rr = 0; rr < 4; rr++) { double dd = s[rr] - mean; ss += dd * dd; }
        double stdv = sqrt(ss * (1.0 / 3.0));   // ddof=1
        g_var[u] = (float)log(stdv + 1.0);
    }

    const float w0 = W[u * 4 + 0], w1 = W[u * 4 + 1];
    const float w2 = W[u * 4 + 2], w3 = W[u * 4 + 3];
    g_uemb[(long)u * 64 + lane]      = w0 * x0s[0] + w1 * x0s[1] + w2 * x0s[2] + w3 * x0s[3];
    g_uemb[(long)u * 64 + lane + 32] = w0 * x1s[0] + w1 * x1s[1] + w2 * x1s[2] + w3 * x1s[3];
}

// ---------------------------------------------------------------------------
// Gather + output. One block per batch element, 64 threads (one per d).
// Output layout: [X_post | X_var_user | AugUser | X_mean_user], each B x D.
// ---------------------------------------------------------------------------
__global__ __launch_bounds__(64) void gather_kernel(
    const float* __restrict__ post_emb,
    const int* __restrict__ src_id,
    const int* __restrict__ rum_id,
    float* __restrict__ out)
{
    const int b = blockIdx.x;
    const int d = threadIdx.x;

    int s = src_id[b];
    long soff = (long)s * 64 + d;
    float p2 = g_p2[soff] + g_p2[1L * P_ * D_ + soff]
             + g_p2[2L * P_ * D_ + soff] + g_p2[3L * P_ * D_ + soff];
    out[(long)b * 64 + d] = (post_emb[soff] + g_p1[soff] + p2) / 3.0f;

    float accv = 0.0f, accm = 0.0f, accu = 0.0f;
#pragma unroll 2
    for (int h = 0; h < H_; h++) {
        int id = rum_id[b * H_ + h];
        long off = (long)id * 64 + d;
        float x = g_Xu[off];            // base = Xu[0]
        float v = g_var[id];
        accv += v * x;
        accm += x;
        accu += g_uemb[off];
    }
    const long BD = (long)B_ * D_;
    out[BD     + (long)b * 64 + d] = accv;
    out[2 * BD + (long)b * 64 + d] = accu * (1.0f / H_);
    out[3 * BD + (long)b * 64 + d] = accm * (1.0f / H_);
}

// ---------------------------------------------------------------------------
extern "C" void kernel_launch(void* const* d_in, const int* in_sizes, int n_in,
                              void* d_out, int out_size)
{
    const float* A0        = (const float*)d_in[0];
    const float* A1        = (const float*)d_in[1];
    const float* A2        = (const float*)d_in[2];
    const float* A3        = (const float*)d_in[3];
    const float* A4        = (const float*)d_in[4];
    const float* user_emb  = (const float*)d_in[5];
    const float* post_emb  = (const float*)d_in[6];
    const float* user_model= (const float*)d_in[7];
    const int*   src_id    = (const int*)d_in[8];
    // d_in[9] = X_user_id (unused by the reference)
    const int*   rum_id    = (const int*)d_in[10];
    float* out = (float*)d_out;

    float *pu1, *pp1, *pXu, *pp2;
    cudaGetSymbolAddress((void**)&pu1, g_u1);
    cudaGetSymbolAddress((void**)&pp1, g_p1);
    cudaGetSymbolAddress((void**)&pXu, g_Xu);
    cudaGetSymbolAddress((void**)&pp2, g_p2);

    Ptr5 a5; a5.p[0] = A0; a5.p[1] = A1; a5.p[2] = A2; a5.p[3] = A3; a5.p[4] = A4;

    const long UD = (long)U_ * D_;
    const long PD = (long)P_ * D_;

    // 1) u1[r] = A_r @ p0              (M=U, K=P)   grid 320
    gemm64_kernel<false, 0, 128><<<dim3(U_ / 128, 1, 5), 256>>>(
        a5, P_, post_emb, 0, pu1, UD, 0, nullptr, nullptr, 0, P_);

    // 2) p1[r] = A_r^T @ u0            (M=P, K=U)   grid 320 (BM=64)
    gemm64_kernel<true, 0, 64><<<dim3(P_ / 64, 1, 5), 256>>>(
        a5, P_, user_emb, 0, pp1, PD, 0, nullptr, nullptr, 0, U_);

    // 3) Xu[r] = (u0 + u1[r] + A_r @ p1[r]) / 3     grid 320
    gemm64_kernel<false, 1, 128><<<dim3(U_ / 128, 1, 5), 256>>>(
        a5, P_, pp1, PD, pXu, UD, 0, user_emb, pu1, UD, P_);

    // 4) p2 partials = A0^T @ u1[0], deterministic split-K=4  grid 256 (BM=64)
    gemm64_kernel<true, 0, 64><<<dim3(P_ / 64, 4, 1), 256>>>(
        a5, P_, pu1, 0, pp2, 0, PD, nullptr, nullptr, 0, U_ / 4);

    // 5) per-user var + user_embedding (fp64 cosine chain)
    user_kernel<<<U_ / 8, 256>>>(user_model);

    // 6) gather outputs
    gather_kernel<<<B_, 64>>>(post_emb, src_id, rum_id, out);
}

// round 4
// speedup vs baseline: 1.5498x; 1.3937x over previous
#include <cuda_runtime.h>
#include <math.h>

// Problem constants
#define U_ 8192
#define P_ 4096
#define D_ 64
#define B_ 1024
#define H_ 50

typedef unsigned long long ull;

// Packed fp32x2 ops (sm_103a): two independent fp32 lanes, bitwise identical
// to scalar FFMA/FADD per element. ptxas never emits these from C++.
#define FMA2(d, a, b) asm("fma.rn.f32x2 %0, %1, %2, %0;" : "+l"(d) : "l"(a), "l"(b))
#define ADD2(d, s)    asm("add.rn.f32x2 %0, %1, %0;" : "+l"(d) : "l"(s))
#define DUP2(d, s)    asm("mov.b64 %0, {%1, %1};"    : "=l"(d) : "f"(s))

// ---------------- scratch (device globals; no allocations allowed) ----------
__device__ float g_u1[5L * U_ * D_];    // u1[r] = A_r @ p0
__device__ float g_p1[10L * P_ * D_];   // p1 split-K=2 partials: [split][r][P][D]
__device__ float g_Xu[5L * U_ * D_];    // Xu[r] = (u0+u1+u2)/3
__device__ float g_p2[4L * P_ * D_];    // split-K=4 partials of A0^T @ u1[0]
__device__ float g_var[U_];
__device__ float g_uemb[(long)U_ * D_];

struct Ptr5 { const float* p[5]; };

// ---------------------------------------------------------------------------
// GEMM: C[M x 64] = op(A) @ (X [+ X2]),  BM=64, BK=32, 256 threads,
// double-buffered smem, thread tile 8m x 2n via fma.rn.f32x2.
//   grid.x: M/64, grid.y: K-split, grid.z: relation r
//   EPI 0: C = acc;  EPI 1: C = (E1 + E2 + acc) / 3
// Per-element FP order inside a K-split: 32-k chunks in order; 32 sequential
// fma.rn into zero-init lacc; one add.rn into acc per chunk (same as round 3).
// ---------------------------------------------------------------------------
template<bool TRANS, int EPI, bool ADDX>
__global__ __launch_bounds__(256, 2) void gemm64_kernel(
    Ptr5 a5, int ldA,
    const float* __restrict__ Xbase, long strideX,
    const float* __restrict__ X2base,
    float* __restrict__ Cbase, long strideCz, long strideCy,
    const float* __restrict__ E1,
    const float* __restrict__ E2base, long strideE2,
    int Kchunk)
{
    const int r = blockIdx.z;
    const float* __restrict__ A  = a5.p[r];
    const float* __restrict__ X  = Xbase + (long)r * strideX;
    const float* __restrict__ X2 = ADDX ? (X2base + (long)r * strideX) : nullptr;
    float* __restrict__ C = Cbase + (long)r * strideCz + (long)blockIdx.y * strideCy;

    const int m0 = blockIdx.x * 64;
    const int kBegin = blockIdx.y * Kchunk;
    const int nChunks = Kchunk / 32;

    __shared__ float As[2][32][68];   // As[buf][k][m], 68: 16B-aligned rows
    __shared__ float Xs[2][32][64];   // Xs[buf][k][n]

    const int tid = threadIdx.x;
    const int tm = tid >> 5;          // 0..7  -> m = tm*8 + i
    const int tn = tid & 31;          // 0..31 -> n = tn*2 + j

    // ---- gmem prefetch registers (one chunk = 32B of A + 32B of X per thread)
    float4 ra[2], rx[2];

    auto loadG = [&](int k0) {
#pragma unroll
        for (int f = 0; f < 2; f++) {
            int linear = tid + 256 * f;
            if (!TRANS) {
                int row = linear >> 3;             // 0..63
                int c4  = (linear & 7) * 4;        // 0..28
                ra[f] = *(const float4*)(A + (size_t)(m0 + row) * ldA + k0 + c4);
            } else {
                int kk = linear >> 4;              // 0..31
                int m4 = (linear & 15) * 4;        // 0..60
                ra[f] = *(const float4*)(A + (size_t)(k0 + kk) * ldA + m0 + m4);
            }
            int kk = linear >> 4;
            int n4 = (linear & 15) * 4;
            float4 v = *(const float4*)(X + (size_t)(k0 + kk) * 64 + n4);
            if (ADDX) {
                float4 w = *(const float4*)(X2 + (size_t)(k0 + kk) * 64 + n4);
                v.x += w.x; v.y += w.y; v.z += w.z; v.w += w.w;
            }
            rx[f] = v;
        }
    };

    auto storeS = [&](int buf) {
#pragma unroll
        for (int f = 0; f < 2; f++) {
            int linear = tid + 256 * f;
            if (!TRANS) {
                int row = linear >> 3;
                int c4  = (linear & 7) * 4;
                As[buf][c4 + 0][row] = ra[f].x;
                As[buf][c4 + 1][row] = ra[f].y;
                As[buf][c4 + 2][row] = ra[f].z;
                As[buf][c4 + 3][row] = ra[f].w;
            } else {
                int kk = linear >> 4;
                int m4 = (linear & 15) * 4;
                *(float4*)&As[buf][kk][m4] = ra[f];
            }
            int kk = linear >> 4;
            int n4 = (linear & 15) * 4;
            *(float4*)&Xs[buf][kk][n4] = rx[f];
        }
    };

    ull acc2[4][2];
#pragma unroll
    for (int p = 0; p < 4; p++) { acc2[p][0] = 0ull; acc2[p][1] = 0ull; }

    // prologue: fill buffer 0
    loadG(kBegin);
    storeS(0);
    __syncthreads();

    int buf = 0;
    for (int c = 0; c < nChunks; c++) {
        if (c + 1 < nChunks) loadG(kBegin + (c + 1) * 32);   // overlap with compute

        ull lacc2[4][2];
#pragma unroll
        for (int p = 0; p < 4; p++) { lacc2[p][0] = 0ull; lacc2[p][1] = 0ull; }

#pragma unroll
        for (int k = 0; k < 32; k++) {
            const ull* ap = (const ull*)&As[buf][k][tm * 8];  // broadcast reads
            ull a0 = ap[0], a1 = ap[1], a2 = ap[2], a3 = ap[3];
            float2 bv = *(const float2*)&Xs[buf][k][tn * 2];
            ull b0, b1;
            DUP2(b0, bv.x); DUP2(b1, bv.y);
            FMA2(lacc2[0][0], a0, b0); FMA2(lacc2[0][1], a0, b1);
            FMA2(lacc2[1][0], a1, b0); FMA2(lacc2[1][1], a1, b1);
            FMA2(lacc2[2][0], a2, b0); FMA2(lacc2[2][1], a2, b1);
            FMA2(lacc2[3][0], a3, b0); FMA2(lacc2[3][1], a3, b1);
        }

#pragma unroll
        for (int p = 0; p < 4; p++) {
            ADD2(acc2[p][0], lacc2[p][0]);
            ADD2(acc2[p][1], lacc2[p][1]);
        }

        if (c + 1 < nChunks) storeS(buf ^ 1);
        __syncthreads();
        buf ^= 1;
    }

    // epilogue
#pragma unroll
    for (int p = 0; p < 4; p++) {
        float2 f0 = *(float2*)&acc2[p][0];
        float2 f1 = *(float2*)&acc2[p][1];
#pragma unroll
        for (int h = 0; h < 2; h++) {
            int m = m0 + tm * 8 + 2 * p + h;
            long off = (long)m * 64 + tn * 2;
            float v0 = h ? f0.y : f0.x;
            float v1 = h ? f1.y : f1.x;
            if (EPI == 1) {
                const float* __restrict__ e2 = E2base + (long)r * strideE2;
                v0 = (E1[off + 0] + e2[off + 0] + v0) / 3.0f;
                v1 = (E1[off + 1] + e2[off + 1] + v1) / 3.0f;
            }
            float2 v; v.x = v0; v.y = v1;
            *(float2*)(C + off) = v;
        }
    }
}

// ---------------------------------------------------------------------------
// Per-user: cosine sims vs 4 relations -> var[u]; user_embedding[u] = W[u,:]@rel
// fp64 chain; round sims to fp32 before the (sim == max) test.
// ---------------------------------------------------------------------------
__global__ __launch_bounds__(256) void user_kernel(const float* __restrict__ W)
{
    const int warp = threadIdx.x >> 5;
    const int lane = threadIdx.x & 31;
    const int u = blockIdx.x * 8 + warp;

    const float* __restrict__ xu0 = g_Xu + (long)u * 64;
    const float b0f = xu0[lane], b1f = xu0[lane + 32];
    const double b0 = (double)b0f, b1 = (double)b1f;

    double d0 = b0 * b0 + b1 * b1;
#pragma unroll
    for (int o = 16; o; o >>= 1) d0 += __shfl_xor_sync(0xffffffffu, d0, o);
    const double n0 = sqrt(d0);

    float sims[4], x0s[4], x1s[4];
#pragma unroll
    for (int rr = 0; rr < 4; rr++) {
        const float* __restrict__ xr = g_Xu + (long)(rr + 1) * U_ * D_ + (long)u * 64;
        float x0 = xr[lane], x1 = xr[lane + 32];
        x0s[rr] = x0; x1s[rr] = x1;
        double xd0 = (double)x0, xd1 = (double)x1;
        double c = b0 * xd0 + b1 * xd1;
        double n = xd0 * xd0 + xd1 * xd1;
#pragma unroll
        for (int o = 16; o; o >>= 1) {
            c += __shfl_xor_sync(0xffffffffu, c, o);
            n += __shfl_xor_sync(0xffffffffu, n, o);
        }
        double denom = n0 * sqrt(n);
        denom = (denom > 1e-8) ? denom : 1e-8;
        sims[rr] = (float)(c / denom);
    }

    if (lane == 0) {
        float mx = fmaxf(fmaxf(sims[0], sims[1]), fmaxf(sims[2], sims[3]));
        double s[4], sum = 0.0;
#pragma unroll
        for (int rr = 0; rr < 4; rr++) {
            s[rr] = (sims[rr] == mx) ? (double)sims[rr] : 0.0;
            sum += s[rr];
        }
        double mean = sum * 0.25;
        double ss = 0.0;
#pragma unroll
        for (int rr = 0; rr < 4; rr++) { double dd = s[rr] - mean; ss += dd * dd; }
        double stdv = sqrt(ss * (1.0 / 3.0));   // ddof=1
        g_var[u] = (float)log(stdv + 1.0);
    }

    const float w0 = W[u * 4 + 0], w1 = W[u * 4 + 1];
    const float w2 = W[u * 4 + 2], w3 = W[u * 4 + 3];
    g_uemb[(long)u * 64 + lane]      = w0 * x0s[0] + w1 * x0s[1] + w2 * x0s[2] + w3 * x0s[3];
    g_uemb[(long)u * 64 + lane + 32] = w0 * x1s[0] + w1 * x1s[1] + w2 * x1s[2] + w3 * x1s[3];
}

// ---------------------------------------------------------------------------
// Gather + output. p1[0] = part0 + part1 (split-K=2); p2 = 4 partials summed.
// ---------------------------------------------------------------------------
__global__ __launch_bounds__(64) void gather_kernel(
    const float* __restrict__ post_emb,
    const int* __restrict__ src_id,
    const int* __restrict__ rum_id,
    float* __restrict__ out)
{
    const int b = blockIdx.x;
    const int d = threadIdx.x;
    const long PD = (long)P_ * D_;

    int s = src_id[b];
    long soff = (long)s * 64 + d;
    float p1v = g_p1[soff] + g_p1[5L * PD + soff];   // part0 + part1 (r=0)
    float p2 = g_p2[soff] + g_p2[1L * PD + soff]
             + g_p2[2L * PD + soff] + g_p2[3L * PD + soff];
    out[(long)b * 64 + d] = (post_emb[soff] + p1v + p2) / 3.0f;

    float accv = 0.0f, accm = 0.0f, accu = 0.0f;
#pragma unroll 2
    for (int h = 0; h < H_; h++) {
        int id = rum_id[b * H_ + h];
        long off = (long)id * 64 + d;
        float x = g_Xu[off];            // base = Xu[0]
        float v = g_var[id];
        accv += v * x;
        accm += x;
        accu += g_uemb[off];
    }
    const long BD = (long)B_ * D_;
    out[BD     + (long)b * 64 + d] = accv;
    out[2 * BD + (long)b * 64 + d] = accu * (1.0f / H_);
    out[3 * BD + (long)b * 64 + d] = accm * (1.0f / H_);
}

// ---------------------------------------------------------------------------
extern "C" void kernel_launch(void* const* d_in, const int* in_sizes, int n_in,
                              void* d_out, int out_size)
{
    const float* A0        = (const float*)d_in[0];
    const float* A1        = (const float*)d_in[1];
    const float* A2        = (const float*)d_in[2];
    const float* A3        = (const float*)d_in[3];
    const float* A4        = (const float*)d_in[4];
    const float* user_emb  = (const float*)d_in[5];
    const float* post_emb  = (const float*)d_in[6];
    const float* user_model= (const float*)d_in[7];
    const int*   src_id    = (const int*)d_in[8];
    // d_in[9] = X_user_id (unused by the reference)
    const int*   rum_id    = (const int*)d_in[10];
    float* out = (float*)d_out;

    float *pu1, *pp1, *pXu, *pp2;
    cudaGetSymbolAddress((void**)&pu1, g_u1);
    cudaGetSymbolAddress((void**)&pp1, g_p1);
    cudaGetSymbolAddress((void**)&pXu, g_Xu);
    cudaGetSymbolAddress((void**)&pp2, g_p2);

    Ptr5 a5; a5.p[0] = A0; a5.p[1] = A1; a5.p[2] = A2; a5.p[3] = A3; a5.p[4] = A4;

    const long UD = (long)U_ * D_;
    const long PD = (long)P_ * D_;

    // 1) u1[r] = A_r @ p0              grid 640, K=4096
    gemm64_kernel<false, 0, false><<<dim3(U_ / 64, 1, 5), 256>>>(
        a5, P_, post_emb, 0, nullptr, pu1, UD, 0, nullptr, nullptr, 0, P_);

    // 2) p1 partials = A_r^T @ u0, split-K=2: layout [split][r][P][D]
    gemm64_kernel<true, 0, false><<<dim3(P_ / 64, 2, 5), 256>>>(
        a5, P_, user_emb, 0, nullptr, pp1, PD, 5 * PD, nullptr, nullptr, 0, U_ / 2);

    // 3) Xu[r] = (u0 + u1[r] + A_r @ (p1_part0 + p1_part1)) / 3    grid 640
    gemm64_kernel<false, 1, true><<<dim3(U_ / 64, 1, 5), 256>>>(
        a5, P_, pp1, PD, pp1 + 5 * PD, pXu, UD, 0, user_emb, pu1, UD, P_);

    // 4) p2 partials = A0^T @ u1[0], split-K=4   grid 256
    gemm64_kernel<true, 0, false><<<dim3(P_ / 64, 4, 1), 256>>>(
        a5, P_, pu1, 0, nullptr, pp2, 0, PD, nullptr, nullptr, 0, U_ / 4);

    // 5) per-user var + user_embedding (fp64 cosine chain)
    user_kernel<<<U_ / 8, 256>>>(user_model);

    // 6) gather outputs
    gather_kernel<<<B_, 64>>>(post_emb, src_id, rum_id, out);
}

// round 5
// speedup vs baseline: 1.7165x; 1.1076x over previous
#include <cuda_runtime.h>
#include <math.h>

// Problem constants
#define U_ 8192
#define P_ 4096
#define D_ 64
#define B_ 1024
#define H_ 50

typedef unsigned long long ull;

// Packed fp32x2 ops (sm_103a): two independent fp32 lanes, bitwise identical
// to scalar FFMA/FADD per element.
#define FMA2(d, a, b) asm("fma.rn.f32x2 %0, %1, %2, %0;" : "+l"(d) : "l"(a), "l"(b))
#define ADD2(d, s)    asm("add.rn.f32x2 %0, %1, %0;" : "+l"(d) : "l"(s))
#define DUP2(d, s)    asm("mov.b64 %0, {%1, %1};"    : "=l"(d) : "f"(s))

// ---------------- scratch (device globals; no allocations allowed) ----------
__device__ float g_u1[5L * U_ * D_];    // u1[r] = A_r @ p0
__device__ float g_p1[10L * P_ * D_];   // p1 split-K=2 partials: [split][r][P][D]
__device__ float g_Xu[5L * U_ * D_];    // Xu[r] = (u0+u1+u2)/3
__device__ float g_p2[8L * P_ * D_];    // split-K=8 partials of A0^T @ u1[0]
__device__ float g_var[U_];
__device__ float g_uemb[(long)U_ * D_];

struct Ptr5 { const float* p[5]; };

// Segment descriptor for the merged GEMM launch. Tile t in a segment decodes:
//   mt = t % mTiles; ks = (t/mTiles) % nSplit; r = (t/mTiles) / nSplit
struct Seg {
    int nTiles, mTiles, nSplit, Kchunk;
    int trans, epi, addx;
    long strideXr;
    const float* Xp; const float* X2p;
    float* Cp; long strideCr; long strideCs;
    const float* E1; const float* E2; long strideE2;
};

// smem layout constants (floats)
#define AROW 132                         // 128 + 4 pad, 16B-aligned rows
#define SM_FLOATS (2 * (32 * AROW + 32 * 64))
#define SM_BYTES  (SM_FLOATS * 4)        // 50176 B -> needs dynamic smem opt-in

// ---------------------------------------------------------------------------
// Merged GEMM: C[128m x 64n] tiles, BK=32, double-buffered, 256 threads.
// Thread tile 16m x 2n: A via 4 broadcast LDS.128, X via lane LDS.64.
// Per-element FP order identical to round 4 (k ascending in 32-chunks,
// zero-init lacc, acc += lacc per chunk).
// ---------------------------------------------------------------------------
__global__ __launch_bounds__(256, 2) void mega_gemm(Ptr5 a5, Seg sa, Seg sb)
{
    extern __shared__ float smem[];
    float (*As)[32][AROW] = (float (*)[32][AROW])smem;
    float (*Xs)[32][64]   = (float (*)[32][64])(smem + 2 * 32 * AROW);

    int t = blockIdx.x;
    const Seg* s = (t < sa.nTiles) ? &sa : &sb;
    if (t >= sa.nTiles) t -= sa.nTiles;

    const int mt   = t % s->mTiles;
    const int rest = t / s->mTiles;
    const int ks   = rest % s->nSplit;
    const int r    = rest / s->nSplit;

    const float* __restrict__ A  = a5.p[r];
    const float* __restrict__ X  = s->Xp + (long)r * s->strideXr;
    const float* __restrict__ X2 = s->addx ? (s->X2p + (long)r * s->strideXr) : nullptr;
    float* __restrict__ C = s->Cp + (long)r * s->strideCr + (long)ks * s->strideCs;

    const int m0 = mt * 128;
    const int kBegin = ks * s->Kchunk;
    const int nChunks = s->Kchunk / 32;
    const bool TRANS = (s->trans != 0);
    const bool ADDX  = (s->addx != 0);

    const int tid = threadIdx.x;
    const int tm = tid >> 5;          // warp id: m-group of 16 rows
    const int tn = tid & 31;          // lane: n-pair index

    float4 ra[4], rx[2];

    auto loadG = [&](int k0) {
        if (!TRANS) {
#pragma unroll
            for (int f = 0; f < 4; f++) {
                int linear = tid + 256 * f;
                int row = linear >> 3;             // 0..127
                int c4  = (linear & 7) * 4;        // 0..28
                ra[f] = *(const float4*)(A + (size_t)(m0 + row) * P_ + k0 + c4);
            }
        } else {
#pragma unroll
            for (int f = 0; f < 4; f++) {
                int linear = tid + 256 * f;
                int kk = linear >> 5;              // 0..31
                int m4 = (linear & 31) * 4;        // 0..124
                ra[f] = *(const float4*)(A + (size_t)(k0 + kk) * P_ + m0 + m4);
            }
        }
#pragma unroll
        for (int f = 0; f < 2; f++) {
            int linear = tid + 256 * f;
            int kk = linear >> 4;
            int n4 = (linear & 15) * 4;
            float4 v = *(const float4*)(X + (size_t)(k0 + kk) * 64 + n4);
            if (ADDX) {
                float4 w = *(const float4*)(X2 + (size_t)(k0 + kk) * 64 + n4);
                v.x += w.x; v.y += w.y; v.z += w.z; v.w += w.w;
            }
            rx[f] = v;
        }
    };

    auto storeS = [&](int buf) {
        if (!TRANS) {
#pragma unroll
            for (int f = 0; f < 4; f++) {
                int linear = tid + 256 * f;
                int row = linear >> 3;
                int c4  = (linear & 7) * 4;
                As[buf][c4 + 0][row] = ra[f].x;
                As[buf][c4 + 1][row] = ra[f].y;
                As[buf][c4 + 2][row] = ra[f].z;
                As[buf][c4 + 3][row] = ra[f].w;
            }
        } else {
#pragma unroll
            for (int f = 0; f < 4; f++) {
                int linear = tid + 256 * f;
                int kk = linear >> 5;
                int m4 = (linear & 31) * 4;
                *(float4*)&As[buf][kk][m4] = ra[f];
            }
        }
#pragma unroll
        for (int f = 0; f < 2; f++) {
            int linear = tid + 256 * f;
            int kk = linear >> 4;
            int n4 = (linear & 15) * 4;
            *(float4*)&Xs[buf][kk][n4] = rx[f];
        }
    };

    ull acc2[8][2];
#pragma unroll
    for (int p = 0; p < 8; p++) { acc2[p][0] = 0ull; acc2[p][1] = 0ull; }

    loadG(kBegin);
    storeS(0);
    __syncthreads();

    int buf = 0;
    for (int c = 0; c < nChunks; c++) {
        if (c + 1 < nChunks) loadG(kBegin + (c + 1) * 32);

        ull lacc2[8][2];
#pragma unroll
        for (int p = 0; p < 8; p++) { lacc2[p][0] = 0ull; lacc2[p][1] = 0ull; }

#pragma unroll
        for (int k = 0; k < 32; k++) {
            const ulonglong2* ap = (const ulonglong2*)&As[buf][k][tm * 16];
            ulonglong2 q0 = ap[0], q1 = ap[1], q2 = ap[2], q3 = ap[3];  // broadcast
            float2 bv = *(const float2*)&Xs[buf][k][tn * 2];
            ull b0, b1;
            DUP2(b0, bv.x); DUP2(b1, bv.y);
            FMA2(lacc2[0][0], q0.x, b0); FMA2(lacc2[0][1], q0.x, b1);
            FMA2(lacc2[1][0], q0.y, b0); FMA2(lacc2[1][1], q0.y, b1);
            FMA2(lacc2[2][0], q1.x, b0); FMA2(lacc2[2][1], q1.x, b1);
            FMA2(lacc2[3][0], q1.y, b0); FMA2(lacc2[3][1], q1.y, b1);
            FMA2(lacc2[4][0], q2.x, b0); FMA2(lacc2[4][1], q2.x, b1);
            FMA2(lacc2[5][0], q2.y, b0); FMA2(lacc2[5][1], q2.y, b1);
            FMA2(lacc2[6][0], q3.x, b0); FMA2(lacc2[6][1], q3.x, b1);
            FMA2(lacc2[7][0], q3.y, b0); FMA2(lacc2[7][1], q3.y, b1);
        }

#pragma unroll
        for (int p = 0; p < 8; p++) {
            ADD2(acc2[p][0], lacc2[p][0]);
            ADD2(acc2[p][1], lacc2[p][1]);
        }

        if (c + 1 < nChunks) storeS(buf ^ 1);
        __syncthreads();
        buf ^= 1;
    }

    const bool EPI = (s->epi != 0);
    const float* __restrict__ E1 = s->E1;
    const float* __restrict__ e2 = EPI ? (s->E2 + (long)r * s->strideE2) : nullptr;

#pragma unroll
    for (int p = 0; p < 8; p++) {
        float2 f0 = *(float2*)&acc2[p][0];
        float2 f1 = *(float2*)&acc2[p][1];
#pragma unroll
        for (int h = 0; h < 2; h++) {
            int m = m0 + tm * 16 + 2 * p + h;
            long off = (long)m * 64 + tn * 2;
            float v0 = h ? f0.y : f0.x;
            float v1 = h ? f1.y : f1.x;
            if (EPI) {
                v0 = (E1[off + 0] + e2[off + 0] + v0) / 3.0f;
                v1 = (E1[off + 1] + e2[off + 1] + v1) / 3.0f;
            }
            float2 v; v.x = v0; v.y = v1;
            *(float2*)(C + off) = v;
        }
    }
}

// ---------------------------------------------------------------------------
// Per-user: cosine sims vs 4 relations -> var[u]; user_embedding.
// fp64 chain; round sims to fp32 before the (sim == max) test.
// ---------------------------------------------------------------------------
__global__ __launch_bounds__(256) void user_kernel(const float* __restrict__ W)
{
    const int warp = threadIdx.x >> 5;
    const int lane = threadIdx.x & 31;
    const int u = blockIdx.x * 8 + warp;

    const float* __restrict__ xu0 = g_Xu + (long)u * 64;
    const float b0f = xu0[lane], b1f = xu0[lane + 32];
    const double b0 = (double)b0f, b1 = (double)b1f;

    double d0 = b0 * b0 + b1 * b1;
#pragma unroll
    for (int o = 16; o; o >>= 1) d0 += __shfl_xor_sync(0xffffffffu, d0, o);
    const double n0 = sqrt(d0);

    float sims[4], x0s[4], x1s[4];
#pragma unroll
    for (int rr = 0; rr < 4; rr++) {
        const float* __restrict__ xr = g_Xu + (long)(rr + 1) * U_ * D_ + (long)u * 64;
        float x0 = xr[lane], x1 = xr[lane + 32];
        x0s[rr] = x0; x1s[rr] = x1;
        double xd0 = (double)x0, xd1 = (double)x1;
        double c = b0 * xd0 + b1 * xd1;
        double n = xd0 * xd0 + xd1 * xd1;
#pragma unroll
        for (int o = 16; o; o >>= 1) {
            c += __shfl_xor_sync(0xffffffffu, c, o);
            n += __shfl_xor_sync(0xffffffffu, n, o);
        }
        double denom = n0 * sqrt(n);
        denom = (denom > 1e-8) ? denom : 1e-8;
        sims[rr] = (float)(c / denom);
    }

    if (lane == 0) {
        float mx = fmaxf(fmaxf(sims[0], sims[1]), fmaxf(sims[2], sims[3]));
        double s[4], sum = 0.0;
#pragma unroll
        for (int rr = 0; rr < 4; rr++) {
            s[rr] = (sims[rr] == mx) ? (double)sims[rr] : 0.0;
            sum += s[rr];
        }
        double mean = sum * 0.25;
        double ss = 0.0;
#pragma unroll
        for (int rr = 0; rr < 4; rr++) { double dd = s[rr] - mean; ss += dd * dd; }
        double stdv = sqrt(ss * (1.0 / 3.0));   // ddof=1
        g_var[u] = (float)log(stdv + 1.0);
    }

    const float w0 = W[u * 4 + 0], w1 = W[u * 4 + 1];
    const float w2 = W[u * 4 + 2], w3 = W[u * 4 + 3];
    g_uemb[(long)u * 64 + lane]      = w0 * x0s[0] + w1 * x0s[1] + w2 * x0s[2] + w3 * x0s[3];
    g_uemb[(long)u * 64 + lane + 32] = w0 * x1s[0] + w1 * x1s[1] + w2 * x1s[2] + w3 * x1s[3];
}

// ---------------------------------------------------------------------------
// Gather + output. p1[0] = part0+part1; p2 = 8 partials summed in order.
// ---------------------------------------------------------------------------
__global__ __launch_bounds__(64) void gather_kernel(
    const float* __restrict__ post_emb,
    const int* __restrict__ src_id,
    const int* __restrict__ rum_id,
    float* __restrict__ out)
{
    const int b = blockIdx.x;
    const int d = threadIdx.x;
    const long PD = (long)P_ * D_;

    int s = src_id[b];
    long soff = (long)s * 64 + d;
    float p1v = g_p1[soff] + g_p1[5L * PD + soff];   // part0 + part1 (r=0)
    float p2 = 0.0f;
#pragma unroll
    for (int sp = 0; sp < 8; sp++) p2 += g_p2[(long)sp * PD + soff];
    out[(long)b * 64 + d] = (post_emb[soff] + p1v + p2) / 3.0f;

    float accv = 0.0f, accm = 0.0f, accu = 0.0f;
#pragma unroll 2
    for (int h = 0; h < H_; h++) {
        int id = rum_id[b * H_ + h];
        long off = (long)id * 64 + d;
        float x = g_Xu[off];            // base = Xu[0]
        float v = g_var[id];
        accv += v * x;
        accm += x;
        accu += g_uemb[off];
    }
    const long BD = (long)B_ * D_;
    out[BD     + (long)b * 64 + d] = accv;
    out[2 * BD + (long)b * 64 + d] = accu * (1.0f / H_);
    out[3 * BD + (long)b * 64 + d] = accm * (1.0f / H_);
}

// ---------------------------------------------------------------------------
extern "C" void kernel_launch(void* const* d_in, const int* in_sizes, int n_in,
                              void* d_out, int out_size)
{
    const float* A0        = (const float*)d_in[0];
    const float* A1        = (const float*)d_in[1];
    const float* A2        = (const float*)d_in[2];
    const float* A3        = (const float*)d_in[3];
    const float* A4        = (const float*)d_in[4];
    const float* user_emb  = (const float*)d_in[5];
    const float* post_emb  = (const float*)d_in[6];
    const float* user_model= (const float*)d_in[7];
    const int*   src_id    = (const int*)d_in[8];
    // d_in[9] = X_user_id (unused by the reference)
    const int*   rum_id    = (const int*)d_in[10];
    float* out = (float*)d_out;

    float *pu1, *pp1, *pXu, *pp2;
    cudaGetSymbolAddress((void**)&pu1, g_u1);
    cudaGetSymbolAddress((void**)&pp1, g_p1);
    cudaGetSymbolAddress((void**)&pXu, g_Xu);
    cudaGetSymbolAddress((void**)&pp2, g_p2);

    Ptr5 a5; a5.p[0] = A0; a5.p[1] = A1; a5.p[2] = A2; a5.p[3] = A3; a5.p[4] = A4;

    const long UD = (long)U_ * D_;
    const long PD = (long)P_ * D_;

    static int smemSet = 0;
    if (!smemSet) {
        cudaFuncSetAttribute(mega_gemm,
                             cudaFuncAttributeMaxDynamicSharedMemorySize, SM_BYTES);
        smemSet = 1;
    }

    // ---- Phase 1: u1 (segA) + p1 split-2 (segB), 640 tiles -----------------
    Seg sa = {};
    sa.nTiles = (U_ / 128) * 5; sa.mTiles = U_ / 128; sa.nSplit = 1; sa.Kchunk = P_;
    sa.trans = 0; sa.epi = 0; sa.addx = 0;
    sa.Xp = post_emb; sa.strideXr = 0; sa.X2p = nullptr;
    sa.Cp = pu1; sa.strideCr = UD; sa.strideCs = 0;
    sa.E1 = nullptr; sa.E2 = nullptr; sa.strideE2 = 0;

    Seg sb = {};
    sb.nTiles = (P_ / 128) * 2 * 5; sb.mTiles = P_ / 128; sb.nSplit = 2; sb.Kchunk = U_ / 2;
    sb.trans = 1; sb.epi = 0; sb.addx = 0;
    sb.Xp = user_emb; sb.strideXr = 0; sb.X2p = nullptr;
    sb.Cp = pp1; sb.strideCr = PD; sb.strideCs = 5 * PD;
    sb.E1 = nullptr; sb.E2 = nullptr; sb.strideE2 = 0;

    mega_gemm<<<sa.nTiles + sb.nTiles, 256, SM_BYTES>>>(a5, sa, sb);

    // ---- Phase 2: Xu (segA) + p2 split-8 (segB), 576 tiles -----------------
    Seg xa = {};
    xa.nTiles = (U_ / 128) * 5; xa.mTiles = U_ / 128; xa.nSplit = 1; xa.Kchunk = P_;
    xa.trans = 0; xa.epi = 1; xa.addx = 1;
    xa.Xp = pp1; xa.strideXr = PD; xa.X2p = pp1 + 5 * PD;
    xa.Cp = pXu; xa.strideCr = UD; xa.strideCs = 0;
    xa.E1 = user_emb; xa.E2 = pu1; xa.strideE2 = UD;

    Seg xb = {};
    xb.nTiles = (P_ / 128) * 8; xb.mTiles = P_ / 128; xb.nSplit = 8; xb.Kchunk = U_ / 8;
    xb.trans = 1; xb.epi = 0; xb.addx = 0;
    xb.Xp = pu1; xb.strideXr = 0; xb.X2p = nullptr;   // r decodes to 0 -> A0, u1[0]
    xb.Cp = pp2; xb.strideCr = 0; xb.strideCs = PD;
    xb.E1 = nullptr; xb.E2 = nullptr; xb.strideE2 = 0;

    mega_gemm<<<xa.nTiles + xb.nTiles, 256, SM_BYTES>>>(a5, xa, xb);

    // ---- Phase 3: epilogue kernels ------------------------------------------
    user_kernel<<<U_ / 8, 256>>>(user_model);
    gather_kernel<<<B_, 64>>>(post_emb, src_id, rum_id, out);
}

// round 6
// speedup vs baseline: 1.9276x; 1.1230x over previous
#include <cuda_runtime.h>
#include <math.h>

// Problem constants
#define U_ 8192
#define P_ 4096
#define D_ 64
#define B_ 1024
#define H_ 50

typedef unsigned long long ull;

// Packed fp32x2 ops (sm_103a): two independent fp32 lanes, bitwise identical
// to scalar FFMA/FADD per element.
#define FMA2(d, a, b) asm("fma.rn.f32x2 %0, %1, %2, %0;" : "+l"(d) : "l"(a), "l"(b))
#define ADD2(d, s)    asm("add.rn.f32x2 %0, %1, %0;" : "+l"(d) : "l"(s))
#define DUP2(d, s)    asm("mov.b64 %0, {%1, %1};"    : "=l"(d) : "f"(s))

// ---------------- scratch (device globals; no allocations allowed) ----------
__device__ float g_u1[5L * U_ * D_];    // u1[r] = A_r @ p0
__device__ float g_p1[10L * P_ * D_];   // p1 split-K=2 partials: [split][r][P][D]
__device__ float g_Xu[5L * U_ * D_];    // Xu[r] = (u0+u1+u2)/3
__device__ float g_p2[8L * P_ * D_];    // split-K=8 partials of A0^T @ u1[0]
__device__ float g_var[U_];
__device__ float g_uemb[(long)U_ * D_];

struct Ptr5 { const float* p[5]; };

// Segment descriptor for the merged GEMM launch. Tile t in a segment decodes:
//   mt = t % mTiles; ks = (t/mTiles) % nSplit; r = (t/mTiles) / nSplit
struct Seg {
    int nTiles, mTiles, nSplit, Kchunk;
    int trans, epi, addx;
    long strideXr;
    const float* Xp; const float* X2p;
    float* Cp; long strideCr; long strideCs;
    const float* E1; const float* E2; long strideE2;
};

// smem layout constants (floats)
#define AROW 132                         // 128 + 4 pad, 16B-aligned rows
#define SM_FLOATS (2 * (32 * AROW + 32 * 64))
#define SM_BYTES  (SM_FLOATS * 4)        // 50176 B -> dynamic smem opt-in

// ---------------------------------------------------------------------------
// Merged GEMM: C[128m x 64n] tiles, BK=32, double-buffered, 256 threads.
// Warp lane geometry: 8 m-groups x 4 n-groups -> thread tile 8m x 4n.
//   A read:  2x LDS.128 at 8 distinct addrs  (1 wavefront each)
//   X read:  1x LDS.128 at 4 distinct addrs  (1 wavefront)
// Per-element FP order identical to rounds 4/5 (k ascending in 32-chunks,
// zero-init lacc, acc += lacc per chunk) -> outputs bit-identical.
// ---------------------------------------------------------------------------
__global__ __launch_bounds__(256, 2) void mega_gemm(Ptr5 a5, Seg sa, Seg sb)
{
    extern __shared__ float smem[];
    float (*As)[32][AROW] = (float (*)[32][AROW])smem;
    float (*Xs)[32][64]   = (float (*)[32][64])(smem + 2 * 32 * AROW);

    int t = blockIdx.x;
    const Seg* s = (t < sa.nTiles) ? &sa : &sb;
    if (t >= sa.nTiles) t -= sa.nTiles;

    const int mt   = t % s->mTiles;
    const int rest = t / s->mTiles;
    const int ks   = rest % s->nSplit;
    const int r    = rest / s->nSplit;

    const float* __restrict__ A  = a5.p[r];
    const float* __restrict__ X  = s->Xp + (long)r * s->strideXr;
    const float* __restrict__ X2 = s->addx ? (s->X2p + (long)r * s->strideXr) : nullptr;
    float* __restrict__ C = s->Cp + (long)r * s->strideCr + (long)ks * s->strideCs;

    const int m0 = mt * 128;
    const int kBegin = ks * s->Kchunk;
    const int nChunks = s->Kchunk / 32;
    const bool TRANS = (s->trans != 0);
    const bool ADDX  = (s->addx != 0);

    const int tid  = threadIdx.x;
    const int wid  = tid >> 5;
    const int lane = tid & 31;
    // warp tile 64m x 16n: warps 2(m) x 4(n); lanes 8(m-groups of 8) x 4(n-groups of 4)
    const int mbase = (wid >> 2) * 64 + (lane >> 2) * 8;   // within CTA tile
    const int nbase = (wid & 3) * 16 + (lane & 3) * 4;

    float4 ra[4], rx[2];

    auto loadG = [&](int k0) {
        if (!TRANS) {
#pragma unroll
            for (int f = 0; f < 4; f++) {
                int linear = tid + 256 * f;
                int row = linear >> 3;             // 0..127
                int c4  = (linear & 7) * 4;        // 0..28
                ra[f] = *(const float4*)(A + (size_t)(m0 + row) * P_ + k0 + c4);
            }
        } else {
#pragma unroll
            for (int f = 0; f < 4; f++) {
                int linear = tid + 256 * f;
                int kk = linear >> 5;              // 0..31
                int m4 = (linear & 31) * 4;        // 0..124
                ra[f] = *(const float4*)(A + (size_t)(k0 + kk) * P_ + m0 + m4);
            }
        }
#pragma unroll
        for (int f = 0; f < 2; f++) {
            int linear = tid + 256 * f;
            int kk = linear >> 4;
            int n4 = (linear & 15) * 4;
            float4 v = *(const float4*)(X + (size_t)(k0 + kk) * 64 + n4);
            if (ADDX) {
                float4 w = *(const float4*)(X2 + (size_t)(k0 + kk) * 64 + n4);
                v.x += w.x; v.y += w.y; v.z += w.z; v.w += w.w;
            }
            rx[f] = v;
        }
    };

    auto storeS = [&](int buf) {
        if (!TRANS) {
#pragma unroll
            for (int f = 0; f < 4; f++) {
                int linear = tid + 256 * f;
                int row = linear >> 3;
                int c4  = (linear & 7) * 4;
                As[buf][c4 + 0][row] = ra[f].x;
                As[buf][c4 + 1][row] = ra[f].y;
                As[buf][c4 + 2][row] = ra[f].z;
                As[buf][c4 + 3][row] = ra[f].w;
            }
        } else {
#pragma unroll
            for (int f = 0; f < 4; f++) {
                int linear = tid + 256 * f;
                int kk = linear >> 5;
                int m4 = (linear & 31) * 4;
                *(float4*)&As[buf][kk][m4] = ra[f];
            }
        }
#pragma unroll
        for (int f = 0; f < 2; f++) {
            int linear = tid + 256 * f;
            int kk = linear >> 4;
            int n4 = (linear & 15) * 4;
            *(float4*)&Xs[buf][kk][n4] = rx[f];
        }
    };

    ull acc2[4][4];                       // [m-pair p][n j]
#pragma unroll
    for (int p = 0; p < 4; p++)
#pragma unroll
        for (int j = 0; j < 4; j++) acc2[p][j] = 0ull;

    loadG(kBegin);
    storeS(0);
    __syncthreads();

    int buf = 0;
    for (int c = 0; c < nChunks; c++) {
        if (c + 1 < nChunks) loadG(kBegin + (c + 1) * 32);

        ull lacc2[4][4];
#pragma unroll
        for (int p = 0; p < 4; p++)
#pragma unroll
            for (int j = 0; j < 4; j++) lacc2[p][j] = 0ull;

#pragma unroll
        for (int k = 0; k < 32; k++) {
            const ulonglong2* ap = (const ulonglong2*)&As[buf][k][mbase];
            ulonglong2 q0 = ap[0], q1 = ap[1];          // m pairs: +0/1,+2/3,+4/5,+6/7
            float4 xv = *(const float4*)&Xs[buf][k][nbase];
            ull b0, b1, b2, b3;
            DUP2(b0, xv.x); DUP2(b1, xv.y); DUP2(b2, xv.z); DUP2(b3, xv.w);
            FMA2(lacc2[0][0], q0.x, b0); FMA2(lacc2[0][1], q0.x, b1);
            FMA2(lacc2[0][2], q0.x, b2); FMA2(lacc2[0][3], q0.x, b3);
            FMA2(lacc2[1][0], q0.y, b0); FMA2(lacc2[1][1], q0.y, b1);
            FMA2(lacc2[1][2], q0.y, b2); FMA2(lacc2[1][3], q0.y, b3);
            FMA2(lacc2[2][0], q1.x, b0); FMA2(lacc2[2][1], q1.x, b1);
            FMA2(lacc2[2][2], q1.x, b2); FMA2(lacc2[2][3], q1.x, b3);
            FMA2(lacc2[3][0], q1.y, b0); FMA2(lacc2[3][1], q1.y, b1);
            FMA2(lacc2[3][2], q1.y, b2); FMA2(lacc2[3][3], q1.y, b3);
        }

#pragma unroll
        for (int p = 0; p < 4; p++)
#pragma unroll
            for (int j = 0; j < 4; j++) ADD2(acc2[p][j], lacc2[p][j]);

        if (c + 1 < nChunks) storeS(buf ^ 1);
        __syncthreads();
        buf ^= 1;
    }

    const bool EPI = (s->epi != 0);
    const float* __restrict__ E1 = s->E1;
    const float* __restrict__ e2 = EPI ? (s->E2 + (long)r * s->strideE2) : nullptr;

#pragma unroll
    for (int p = 0; p < 4; p++) {
        float2 f[4];
#pragma unroll
        for (int j = 0; j < 4; j++) f[j] = *(float2*)&acc2[p][j];
#pragma unroll
        for (int h = 0; h < 2; h++) {
            int m = m0 + mbase + 2 * p + h;
            long off = (long)m * 64 + nbase;
            float4 v;
            v.x = h ? f[0].y : f[0].x;
            v.y = h ? f[1].y : f[1].x;
            v.z = h ? f[2].y : f[2].x;
            v.w = h ? f[3].y : f[3].x;
            if (EPI) {
                v.x = (E1[off + 0] + e2[off + 0] + v.x) / 3.0f;
                v.y = (E1[off + 1] + e2[off + 1] + v.y) / 3.0f;
                v.z = (E1[off + 2] + e2[off + 2] + v.z) / 3.0f;
                v.w = (E1[off + 3] + e2[off + 3] + v.w) / 3.0f;
            }
            *(float4*)(C + off) = v;
        }
    }
}

// ---------------------------------------------------------------------------
// Per-user: cosine sims vs 4 relations -> var[u]; user_embedding.
// fp64 chain; round sims to fp32 before the (sim == max) test.
// ---------------------------------------------------------------------------
__global__ __launch_bounds__(256) void user_kernel(const float* __restrict__ W)
{
    const int warp = threadIdx.x >> 5;
    const int lane = threadIdx.x & 31;
    const int u = blockIdx.x * 8 + warp;

    const float* __restrict__ xu0 = g_Xu + (long)u * 64;
    const float b0f = xu0[lane], b1f = xu0[lane + 32];
    const double b0 = (double)b0f, b1 = (double)b1f;

    double d0 = b0 * b0 + b1 * b1;
#pragma unroll
    for (int o = 16; o; o >>= 1) d0 += __shfl_xor_sync(0xffffffffu, d0, o);
    const double n0 = sqrt(d0);

    float sims[4], x0s[4], x1s[4];
#pragma unroll
    for (int rr = 0; rr < 4; rr++) {
        const float* __restrict__ xr = g_Xu + (long)(rr + 1) * U_ * D_ + (long)u * 64;
        float x0 = xr[lane], x1 = xr[lane + 32];
        x0s[rr] = x0; x1s[rr] = x1;
        double xd0 = (double)x0, xd1 = (double)x1;
        double c = b0 * xd0 + b1 * xd1;
        double n = xd0 * xd0 + xd1 * xd1;
#pragma unroll
        for (int o = 16; o; o >>= 1) {
            c += __shfl_xor_sync(0xffffffffu, c, o);
            n += __shfl_xor_sync(0xffffffffu, n, o);
        }
        double denom = n0 * sqrt(n);
        denom = (denom > 1e-8) ? denom : 1e-8;
        sims[rr] = (float)(c / denom);
    }

    if (lane == 0) {
        float mx = fmaxf(fmaxf(sims[0], sims[1]), fmaxf(sims[2], sims[3]));
        double s[4], sum = 0.0;
#pragma unroll
        for (int rr = 0; rr < 4; rr++) {
            s[rr] = (sims[rr] == mx) ? (double)sims[rr] : 0.0;
            sum += s[rr];
        }
        double mean = sum * 0.25;
        double ss = 0.0;
#pragma unroll
        for (int rr = 0; rr < 4; rr++) { double dd = s[rr] - mean; ss += dd * dd; }
        double stdv = sqrt(ss * (1.0 / 3.0));   // ddof=1
        g_var[u] = (float)log(stdv + 1.0);
    }

    const float w0 = W[u * 4 + 0], w1 = W[u * 4 + 1];
    const float w2 = W[u * 4 + 2], w3 = W[u * 4 + 3];
    g_uemb[(long)u * 64 + lane]      = w0 * x0s[0] + w1 * x0s[1] + w2 * x0s[2] + w3 * x0s[3];
    g_uemb[(long)u * 64 + lane + 32] = w0 * x1s[0] + w1 * x1s[1] + w2 * x1s[2] + w3 * x1s[3];
}

// ---------------------------------------------------------------------------
// Gather + output. p1[0] = part0+part1; p2 = 8 partials summed in order.
// ---------------------------------------------------------------------------
__global__ __launch_bounds__(64) void gather_kernel(
    const float* __restrict__ post_emb,
    const int* __restrict__ src_id,
    const int* __restrict__ rum_id,
    float* __restrict__ out)
{
    const int b = blockIdx.x;
    const int d = threadIdx.x;
    const long PD = (long)P_ * D_;

    int s = src_id[b];
    long soff = (long)s * 64 + d;
    float p1v = g_p1[soff] + g_p1[5L * PD + soff];   // part0 + part1 (r=0)
    float p2 = 0.0f;
#pragma unroll
    for (int sp = 0; sp < 8; sp++) p2 += g_p2[(long)sp * PD + soff];
    out[(long)b * 64 + d] = (post_emb[soff] + p1v + p2) / 3.0f;

    float accv = 0.0f, accm = 0.0f, accu = 0.0f;
#pragma unroll 2
    for (int h = 0; h < H_; h++) {
        int id = rum_id[b * H_ + h];
        long off = (long)id * 64 + d;
        float x = g_Xu[off];            // base = Xu[0]
        float v = g_var[id];
        accv += v * x;
        accm += x;
        accu += g_uemb[off];
    }
    const long BD = (long)B_ * D_;
    out[BD     + (long)b * 64 + d] = accv;
    out[2 * BD + (long)b * 64 + d] = accu * (1.0f / H_);
    out[3 * BD + (long)b * 64 + d] = accm * (1.0f / H_);
}

// ---------------------------------------------------------------------------
extern "C" void kernel_launch(void* const* d_in, const int* in_sizes, int n_in,
                              void* d_out, int out_size)
{
    const float* A0        = (const float*)d_in[0];
    const float* A1        = (const float*)d_in[1];
    const float* A2        = (const float*)d_in[2];
    const float* A3        = (const float*)d_in[3];
    const float* A4        = (const float*)d_in[4];
    const float* user_emb  = (const float*)d_in[5];
    const float* post_emb  = (const float*)d_in[6];
    const float* user_model= (const float*)d_in[7];
    const int*   src_id    = (const int*)d_in[8];
    // d_in[9] = X_user_id (unused by the reference)
    const int*   rum_id    = (const int*)d_in[10];
    float* out = (float*)d_out;

    float *pu1, *pp1, *pXu, *pp2;
    cudaGetSymbolAddress((void**)&pu1, g_u1);
    cudaGetSymbolAddress((void**)&pp1, g_p1);
    cudaGetSymbolAddress((void**)&pXu, g_Xu);
    cudaGetSymbolAddress((void**)&pp2, g_p2);

    Ptr5 a5; a5.p[0] = A0; a5.p[1] = A1; a5.p[2] = A2; a5.p[3] = A3; a5.p[4] = A4;

    const long UD = (long)U_ * D_;
    const long PD = (long)P_ * D_;

    static int smemSet = 0;
    if (!smemSet) {
        cudaFuncSetAttribute(mega_gemm,
                             cudaFuncAttributeMaxDynamicSharedMemorySize, SM_BYTES);
        smemSet = 1;
    }

    // ---- Phase 1: u1 (segA) + p1 split-2 (segB), 640 tiles -----------------
    Seg sa = {};
    sa.nTiles = (U_ / 128) * 5; sa.mTiles = U_ / 128; sa.nSplit = 1; sa.Kchunk = P_;
    sa.trans = 0; sa.epi = 0; sa.addx = 0;
    sa.Xp = post_emb; sa.strideXr = 0; sa.X2p = nullptr;
    sa.Cp = pu1; sa.strideCr = UD; sa.strideCs = 0;
    sa.E1 = nullptr; sa.E2 = nullptr; sa.strideE2 = 0;

    Seg sb = {};
    sb.nTiles = (P_ / 128) * 2 * 5; sb.mTiles = P_ / 128; sb.nSplit = 2; sb.Kchunk = U_ / 2;
    sb.trans = 1; sb.epi = 0; sb.addx = 0;
    sb.Xp = user_emb; sb.strideXr = 0; sb.X2p = nullptr;
    sb.Cp = pp1; sb.strideCr = PD; sb.strideCs = 5 * PD;
    sb.E1 = nullptr; sb.E2 = nullptr; sb.strideE2 = 0;

    mega_gemm<<<sa.nTiles + sb.nTiles, 256, SM_BYTES>>>(a5, sa, sb);

    // ---- Phase 2: Xu (segA) + p2 split-8 (segB), 576 tiles -----------------
    Seg xa = {};
    xa.nTiles = (U_ / 128) * 5; xa.mTiles = U_ / 128; xa.nSplit = 1; xa.Kchunk = P_;
    xa.trans = 0; xa.epi = 1; xa.addx = 1;
    xa.Xp = pp1; xa.strideXr = PD; xa.X2p = pp1 + 5 * PD;
    xa.Cp = pXu; xa.strideCr = UD; xa.strideCs = 0;
    xa.E1 = user_emb; xa.E2 = pu1; xa.strideE2 = UD;

    Seg xb = {};
    xb.nTiles = (P_ / 128) * 8; xb.mTiles = P_ / 128; xb.nSplit = 8; xb.Kchunk = U_ / 8;
    xb.trans = 1; xb.epi = 0; xb.addx = 0;
    xb.Xp = pu1; xb.strideXr = 0; xb.X2p = nullptr;   // r decodes to 0 -> A0, u1[0]
    xb.Cp = pp2; xb.strideCr = 0; xb.strideCs = PD;
    xb.E1 = nullptr; xb.E2 = nullptr; xb.strideE2 = 0;

    mega_gemm<<<xa.nTiles + xb.nTiles, 256, SM_BYTES>>>(a5, xa, xb);

    // ---- Phase 3: epilogue kernels ------------------------------------------
    user_kernel<<<U_ / 8, 256>>>(user_model);
    gather_kernel<<<B_, 64>>>(post_emb, src_id, rum_id, out);
}